// round 2
// baseline (speedup 1.0000x reference)
#include <cuda_runtime.h>
#include <math.h>

// ============================================================================
// MultiHeadAttention: x[2,2048,768] -> out[2,2048,768]
//   q/k/v = x @ W^T + b   (W: [768,768] row-major; y[e] = sum_d x[d]*W[e,d])
//   per (b,h): softmax(Q K^T / sqrt(64)) V
//   out = ctx @ Wo^T + bo
// fp32 everywhere (rel_err < 1e-3 gate). FMA-pipe-bound baseline.
// R2: SGEMM upgraded to 128x128x16 (8x8/thread), QKV fused into one launch.
// ============================================================================

#define BATCH 2
#define SEQ   2048
#define DM    768
#define NH    12
#define DKH   64
#define MTOK  (BATCH*SEQ)   // 4096

// Scratch (allocation-free contract: __device__ globals)
__device__ float g_q[MTOK*DM];
__device__ float g_k[MTOK*DM];
__device__ float g_v[MTOK*DM];
__device__ float g_ctx[MTOK*DM];

// ----------------------------------------------------------------------------
// SGEMM with bias: Y[M,N] = X[M,K] @ W[N,K]^T + bias[N]
// M=4096, N=768, K=768. BM=BN=128, BK=16, 256 threads, 8x8 per thread.
// ----------------------------------------------------------------------------
#define GK 768
#define GN 768
#define BM 128
#define BN 128
#define BKK 16

__device__ __forceinline__ void sgemm_tile(
    const float* __restrict__ X, const float* __restrict__ W,
    const float* __restrict__ bias, float* __restrict__ Y,
    int m0, int n0)
{
    __shared__ float As[BKK][BM];   // As[k][m]  (8 KB)
    __shared__ float Bs[BKK][BN];   // Bs[k][n]  (8 KB)

    const int tid = threadIdx.x;
    const int tx = tid & 15;   // n: 16 groups of 8
    const int ty = tid >> 4;   // m: 16 groups of 8

    float acc[8][8];
#pragma unroll
    for (int i = 0; i < 8; i++)
#pragma unroll
        for (int j = 0; j < 8; j++) acc[i][j] = 0.f;

    for (int k0 = 0; k0 < GK; k0 += BKK) {
        // A tile: 128 rows x 16 k = 512 float4, 2 per thread
#pragma unroll
        for (int i = 0; i < 2; i++) {
            int f = tid + i * 256;
            int r = f >> 2;
            int c4 = (f & 3) * 4;
            float4 av = *(const float4*)&X[(m0 + r) * GK + k0 + c4];
            As[c4 + 0][r] = av.x;
            As[c4 + 1][r] = av.y;
            As[c4 + 2][r] = av.z;
            As[c4 + 3][r] = av.w;
        }
        // B tile: 128 n-rows x 16 k = 512 float4, 2 per thread
#pragma unroll
        for (int i = 0; i < 2; i++) {
            int f = tid + i * 256;
            int r = f >> 2;
            int c4 = (f & 3) * 4;
            float4 bv = *(const float4*)&W[(n0 + r) * GK + k0 + c4];
            Bs[c4 + 0][r] = bv.x;
            Bs[c4 + 1][r] = bv.y;
            Bs[c4 + 2][r] = bv.z;
            Bs[c4 + 3][r] = bv.w;
        }
        __syncthreads();

#pragma unroll
        for (int k = 0; k < BKK; k++) {
            float4 a0 = *(const float4*)&As[k][ty * 8];
            float4 a1 = *(const float4*)&As[k][ty * 8 + 4];
            float4 b0 = *(const float4*)&Bs[k][tx * 8];
            float4 b1 = *(const float4*)&Bs[k][tx * 8 + 4];
            float am[8] = {a0.x, a0.y, a0.z, a0.w, a1.x, a1.y, a1.z, a1.w};
            float bn[8] = {b0.x, b0.y, b0.z, b0.w, b1.x, b1.y, b1.z, b1.w};
#pragma unroll
            for (int i = 0; i < 8; i++)
#pragma unroll
                for (int j = 0; j < 8; j++)
                    acc[i][j] = fmaf(am[i], bn[j], acc[i][j]);
        }
        __syncthreads();
    }

    float bb[8];
#pragma unroll
    for (int j = 0; j < 8; j++) bb[j] = bias[n0 + tx * 8 + j];

#pragma unroll
    for (int i = 0; i < 8; i++) {
        int m = m0 + ty * 8 + i;
        float4 o0, o1;
        o0.x = acc[i][0] + bb[0]; o0.y = acc[i][1] + bb[1];
        o0.z = acc[i][2] + bb[2]; o0.w = acc[i][3] + bb[3];
        o1.x = acc[i][4] + bb[4]; o1.y = acc[i][5] + bb[5];
        o1.z = acc[i][6] + bb[6]; o1.w = acc[i][7] + bb[7];
        *(float4*)&Y[m * GN + n0 + tx * 8]     = o0;
        *(float4*)&Y[m * GN + n0 + tx * 8 + 4] = o1;
    }
}

// Fused Q/K/V projection: gridDim.z selects which weight/bias/output.
__global__ void __launch_bounds__(256) qkv_gemm_kernel(
    const float* __restrict__ X,
    const float* __restrict__ Wq, const float* __restrict__ bq, float* __restrict__ Yq,
    const float* __restrict__ Wk, const float* __restrict__ bk, float* __restrict__ Yk,
    const float* __restrict__ Wv, const float* __restrict__ bv, float* __restrict__ Yv)
{
    const float* W; const float* b; float* Y;
    if (blockIdx.z == 0)      { W = Wq; b = bq; Y = Yq; }
    else if (blockIdx.z == 1) { W = Wk; b = bk; Y = Yk; }
    else                      { W = Wv; b = bv; Y = Yv; }
    sgemm_tile(X, W, b, Y, blockIdx.y * BM, blockIdx.x * BN);
}

__global__ void __launch_bounds__(256) out_gemm_kernel(
    const float* __restrict__ X, const float* __restrict__ W,
    const float* __restrict__ bias, float* __restrict__ Y)
{
    sgemm_tile(X, W, bias, Y, blockIdx.y * BM, blockIdx.x * BN);
}

// ----------------------------------------------------------------------------
// Flash attention (fp32, online softmax).
// Block: 256 threads, TQ=128 queries, TK=64 keys/tile, d_k=64.
// Grid: (SEQ/128, NH, BATCH) = (16, 12, 2).
// ----------------------------------------------------------------------------
struct AttnSmem {
    float Qt[DKH][128];    // [d][q], pre-scaled by 1/sqrt(d_k)
    float Kt[DKH][64];     // [d][k]
    float Vt[64][DKH];     // [k][d]
    float S[128][65];      // scores -> probs
    float mrow[128];
    float lrow[128];
    float crow[128];
};

__global__ void __launch_bounds__(256) attn_kernel(
    const float* __restrict__ Q, const float* __restrict__ K,
    const float* __restrict__ V, float* __restrict__ CTX)
{
    extern __shared__ char smem_raw[];
    AttnSmem& sm = *reinterpret_cast<AttnSmem*>(smem_raw);

    const int tid = threadIdx.x;
    const int b = blockIdx.z, h = blockIdx.y;
    const int q0 = blockIdx.x * 128;
    const int tx = tid & 15;   // 16 groups of 4 (k / d_k dim)
    const int ty = tid >> 4;   // 16 groups of 8 (q dim)
    const float scale = 0.125f;  // 1/sqrt(64)

    // Load Q tile transposed + pre-scaled: 128x64 = 2048 float4, 8/thread
#pragma unroll
    for (int i = 0; i < 8; i++) {
        int f = tid + i * 256;
        int qr = f >> 4;
        int c4 = (f & 15) * 4;
        float4 v = *(const float4*)&Q[(b * SEQ + q0 + qr) * DM + h * DKH + c4];
        sm.Qt[c4 + 0][qr] = v.x * scale;
        sm.Qt[c4 + 1][qr] = v.y * scale;
        sm.Qt[c4 + 2][qr] = v.z * scale;
        sm.Qt[c4 + 3][qr] = v.w * scale;
    }
    if (tid < 128) {
        sm.mrow[tid] = -INFINITY;
        sm.lrow[tid] = 0.f;
    }

    float oacc[8][4];
#pragma unroll
    for (int i = 0; i < 8; i++)
#pragma unroll
        for (int j = 0; j < 4; j++) oacc[i][j] = 0.f;

    __syncthreads();

    for (int kt = 0; kt < SEQ / 64; kt++) {
        const int sk0 = kt * 64;
        // Load K (transposed) and V (natural): 64x64 each = 1024 float4, 4/thread
#pragma unroll
        for (int i = 0; i < 4; i++) {
            int f = tid + i * 256;
            int r = f >> 4;
            int c4 = (f & 15) * 4;
            int g = (b * SEQ + sk0 + r) * DM + h * DKH + c4;
            float4 kv = *(const float4*)&K[g];
            sm.Kt[c4 + 0][r] = kv.x;
            sm.Kt[c4 + 1][r] = kv.y;
            sm.Kt[c4 + 2][r] = kv.z;
            sm.Kt[c4 + 3][r] = kv.w;
            *(float4*)&sm.Vt[r][c4] = *(const float4*)&V[g];
        }
        __syncthreads();

        // Scores: S[128x64] = Qt^T Kt, 8x4 per thread
        float sreg[8][4];
#pragma unroll
        for (int i = 0; i < 8; i++)
#pragma unroll
            for (int j = 0; j < 4; j++) sreg[i][j] = 0.f;

#pragma unroll 8
        for (int d = 0; d < DKH; d++) {
            float4 qa0 = *(const float4*)&sm.Qt[d][ty * 8];
            float4 qa1 = *(const float4*)&sm.Qt[d][ty * 8 + 4];
            float4 kb  = *(const float4*)&sm.Kt[d][tx * 4];
            float qq[8] = {qa0.x, qa0.y, qa0.z, qa0.w, qa1.x, qa1.y, qa1.z, qa1.w};
            float kk[4] = {kb.x, kb.y, kb.z, kb.w};
#pragma unroll
            for (int i = 0; i < 8; i++)
#pragma unroll
                for (int j = 0; j < 4; j++)
                    sreg[i][j] = fmaf(qq[i], kk[j], sreg[i][j]);
        }
#pragma unroll
        for (int i = 0; i < 8; i++)
#pragma unroll
            for (int j = 0; j < 4; j++)
                sm.S[ty * 8 + i][tx * 4 + j] = sreg[i][j];
        __syncthreads();

        // Online softmax: 2 threads per row, 32 cols each
        {
            int q = tid >> 1;
            int half = tid & 1;
            int c0 = half * 32;
            float pm = -INFINITY;
#pragma unroll 8
            for (int c = 0; c < 32; c++) pm = fmaxf(pm, sm.S[q][c0 + c]);
            pm = fmaxf(pm, __shfl_xor_sync(0xffffffffu, pm, 1));
            float oldm = sm.mrow[q];
            float newm = fmaxf(oldm, pm);
            float corr = __expf(oldm - newm);
            float ps = 0.f;
#pragma unroll 8
            for (int c = 0; c < 32; c++) {
                float p = __expf(sm.S[q][c0 + c] - newm);
                sm.S[q][c0 + c] = p;
                ps += p;
            }
            ps += __shfl_xor_sync(0xffffffffu, ps, 1);
            if (half == 0) {
                sm.mrow[q] = newm;
                sm.lrow[q] = sm.lrow[q] * corr + ps;
                sm.crow[q] = corr;
            }
        }
        __syncthreads();

        // O update: rescale + P @ V, 8x4 per thread
        float cf[8];
#pragma unroll
        for (int i = 0; i < 8; i++) cf[i] = sm.crow[ty * 8 + i];
#pragma unroll
        for (int i = 0; i < 8; i++)
#pragma unroll
            for (int j = 0; j < 4; j++) oacc[i][j] *= cf[i];

#pragma unroll 8
        for (int k = 0; k < 64; k++) {
            float4 v4 = *(const float4*)&sm.Vt[k][tx * 4];
            float vv[4] = {v4.x, v4.y, v4.z, v4.w};
#pragma unroll
            for (int i = 0; i < 8; i++) {
                float p = sm.S[ty * 8 + i][k];
#pragma unroll
                for (int j = 0; j < 4; j++)
                    oacc[i][j] = fmaf(p, vv[j], oacc[i][j]);
            }
        }
        __syncthreads();  // protect Kt/Vt/S for next tile
    }

    // Epilogue: divide by l, write ctx[b][s][h*64+d]
#pragma unroll
    for (int i = 0; i < 8; i++) {
        int q = ty * 8 + i;
        float inv = 1.0f / sm.lrow[q];
        float4 o;
        o.x = oacc[i][0] * inv;
        o.y = oacc[i][1] * inv;
        o.z = oacc[i][2] * inv;
        o.w = oacc[i][3] * inv;
        *(float4*)&CTX[(b * SEQ + q0 + q) * DM + h * DKH + tx * 4] = o;
    }
}

// ----------------------------------------------------------------------------
// Launch
// ----------------------------------------------------------------------------
extern "C" void kernel_launch(void* const* d_in, const int* in_sizes, int n_in,
                              void* d_out, int out_size)
{
    (void)in_sizes; (void)n_in; (void)out_size;
    const float* x   = (const float*)d_in[0];
    const float* w_q = (const float*)d_in[1];
    const float* b_q = (const float*)d_in[2];
    const float* w_k = (const float*)d_in[3];
    const float* b_k = (const float*)d_in[4];
    const float* w_v = (const float*)d_in[5];
    const float* b_v = (const float*)d_in[6];
    const float* w_o = (const float*)d_in[7];
    const float* b_o = (const float*)d_in[8];
    float* out = (float*)d_out;

    float *q, *k, *v, *ctx;
    cudaGetSymbolAddress((void**)&q,   g_q);
    cudaGetSymbolAddress((void**)&k,   g_k);
    cudaGetSymbolAddress((void**)&v,   g_v);
    cudaGetSymbolAddress((void**)&ctx, g_ctx);

    dim3 gqkv(GN / BN, MTOK / BM, 3);   // (6, 32, 3) = 576 blocks
    qkv_gemm_kernel<<<gqkv, 256>>>(x, w_q, b_q, q, w_k, b_k, k, w_v, b_v, v);

    cudaFuncSetAttribute(attn_kernel,
                         cudaFuncAttributeMaxDynamicSharedMemorySize,
                         (int)sizeof(AttnSmem));
    attn_kernel<<<dim3(SEQ / 128, NH, BATCH), 256, sizeof(AttnSmem)>>>(q, k, v, ctx);

    dim3 go(GN / BN, MTOK / BM);        // (6, 32)
    out_gemm_kernel<<<go, 256>>>(ctx, w_o, b_o, out);
}

// round 5
// speedup vs baseline: 1.3000x; 1.3000x over previous
#include <cuda_runtime.h>
#include <cuda_bf16.h>
#include <math.h>
#include <stdint.h>

// ============================================================================
// MultiHeadAttention: x[2,2048,768] -> out[2,2048,768]
// R5: harness compiles for plain sm_100 (no tcgen05!). Projection GEMMs use
// legacy tensor path: mma.sync.m16n8k16 bf16 with 3-way precision split
// (Ah*Bh + Ah*Bl + Al*Bh, fp32 accum). cp.async double-buffered smem,
// ldmatrix fragment loads. Attention = known-passing fp32 flash (R2).
// ============================================================================

#define BATCH 2
#define SEQ   2048
#define DM    768
#define NH    12
#define DKH   64
#define MTOK  (BATCH*SEQ)   // 4096

// fp32 scratch
__device__ float g_q[MTOK*DM];
__device__ float g_k[MTOK*DM];
__device__ float g_v[MTOK*DM];
__device__ float g_ctx[MTOK*DM];

// bf16 hi/lo scratch
__device__ __nv_bfloat16 g_xh[MTOK*DM],  g_xl[MTOK*DM];
__device__ __nv_bfloat16 g_ch[MTOK*DM],  g_cl[MTOK*DM];
__device__ __nv_bfloat16 g_wqh[DM*DM], g_wql[DM*DM];
__device__ __nv_bfloat16 g_wkh[DM*DM], g_wkl[DM*DM];
__device__ __nv_bfloat16 g_wvh[DM*DM], g_wvl[DM*DM];
__device__ __nv_bfloat16 g_woh[DM*DM], g_wol[DM*DM];

// ----------------------------------------------------------------------------
// fp32 -> bf16 hi/lo split
// ----------------------------------------------------------------------------
__device__ __forceinline__ void cvt_hilo_body(
    const float* __restrict__ s, __nv_bfloat16* __restrict__ hi,
    __nv_bfloat16* __restrict__ lo, int n4, int i)
{
    if (i >= n4) return;
    float4 v = ((const float4*)s)[i];
    float f[4] = {v.x, v.y, v.z, v.w};
    __nv_bfloat162 h2[2], l2[2];
#pragma unroll
    for (int j = 0; j < 2; j++) {
        __nv_bfloat16 h0 = __float2bfloat16(f[2*j]);
        __nv_bfloat16 h1 = __float2bfloat16(f[2*j+1]);
        __nv_bfloat16 l0 = __float2bfloat16(f[2*j]   - __bfloat162float(h0));
        __nv_bfloat16 l1 = __float2bfloat16(f[2*j+1] - __bfloat162float(h1));
        h2[j] = __halves2bfloat162(h0, h1);
        l2[j] = __halves2bfloat162(l0, l1);
    }
    ((__nv_bfloat162*)hi)[2*i]   = h2[0];
    ((__nv_bfloat162*)hi)[2*i+1] = h2[1];
    ((__nv_bfloat162*)lo)[2*i]   = l2[0];
    ((__nv_bfloat162*)lo)[2*i+1] = l2[1];
}

__global__ void __launch_bounds__(256) cvt_hilo_kernel(
    const float* __restrict__ s, __nv_bfloat16* __restrict__ hi,
    __nv_bfloat16* __restrict__ lo, int n4)
{
    cvt_hilo_body(s, hi, lo, n4, blockIdx.x * blockDim.x + threadIdx.x);
}

__global__ void __launch_bounds__(256) cvt_w4_kernel(
    const float* __restrict__ s0, __nv_bfloat16* __restrict__ h0, __nv_bfloat16* __restrict__ l0,
    const float* __restrict__ s1, __nv_bfloat16* __restrict__ h1, __nv_bfloat16* __restrict__ l1,
    const float* __restrict__ s2, __nv_bfloat16* __restrict__ h2, __nv_bfloat16* __restrict__ l2,
    const float* __restrict__ s3, __nv_bfloat16* __restrict__ h3, __nv_bfloat16* __restrict__ l3,
    int n4)
{
    const float* s; __nv_bfloat16 *h, *l;
    switch (blockIdx.y) {
        case 0: s = s0; h = h0; l = l0; break;
        case 1: s = s1; h = h1; l = l1; break;
        case 2: s = s2; h = h2; l = l2; break;
        default: s = s3; h = h3; l = l3; break;
    }
    cvt_hilo_body(s, h, l, n4, blockIdx.x * blockDim.x + threadIdx.x);
}

// ----------------------------------------------------------------------------
// mma.sync bf16 3-split GEMM: Y[M,768] = Ah@Bh^T + Ah@Bl^T + Al@Bh^T + bias
// A: [M,768] bf16 K-major; B: [768,768] bf16 K-major (rows = output dim).
// CTA 128x128, BK=32, 256 threads (8 warps as 4m x 2n; warp tile 32x64).
// smem rows padded to 40 bf16 (80B stride -> conflict-free ldmatrix).
// ----------------------------------------------------------------------------
#define MM_ROWB   80                        // bytes per padded smem row
#define MM_ARR    10240                     // 128 rows * 80B
#define MM_STAGE  (4*MM_ARR)                // Ah|Al|Bh|Bl
#define MM_SMEM   (2*MM_STAGE)              // 81920 B double-buffered

__device__ __forceinline__ uint32_t smem_u32(const void* p) {
    uint32_t a;
    asm("{ .reg .u64 t; cvta.to.shared.u64 t, %1; cvt.u32.u64 %0, t; }"
        : "=r"(a) : "l"(p));
    return a;
}
__device__ __forceinline__ void cp16(uint32_t dst, const void* src) {
    asm volatile("cp.async.cg.shared.global [%0], [%1], 16;"
                 :: "r"(dst), "l"(src) : "memory");
}
__device__ __forceinline__ void ldsm4(uint32_t* r, uint32_t addr) {
    asm volatile("ldmatrix.sync.aligned.m8n8.x4.shared.b16 {%0,%1,%2,%3}, [%4];"
                 : "=r"(r[0]), "=r"(r[1]), "=r"(r[2]), "=r"(r[3]) : "r"(addr));
}
__device__ __forceinline__ void mma16816(float* c, const uint32_t* a,
                                         uint32_t b0, uint32_t b1) {
    asm volatile(
        "mma.sync.aligned.m16n8k16.row.col.f32.bf16.bf16.f32 "
        "{%0,%1,%2,%3}, {%4,%5,%6,%7}, {%8,%9}, {%0,%1,%2,%3};"
        : "+f"(c[0]), "+f"(c[1]), "+f"(c[2]), "+f"(c[3])
        : "r"(a[0]), "r"(a[1]), "r"(a[2]), "r"(a[3]), "r"(b0), "r"(b1));
}

// stage in smem: [Ah | Al | Bh | Bl], each 128 rows x 32 bf16 (padded to 40)
__device__ __forceinline__ void mm_load_chunk(
    const __nv_bfloat16* __restrict__ Ah, const __nv_bfloat16* __restrict__ Al,
    const __nv_bfloat16* __restrict__ Bh, const __nv_bfloat16* __restrict__ Bl,
    int m0, int n0, int k0, uint32_t stage, int tid)
{
    const __nv_bfloat16* srcs[4] = {Ah, Al, Bh, Bl};
    const int r0s[4] = {m0, m0, n0, n0};
#pragma unroll
    for (int a = 0; a < 4; a++) {
#pragma unroll
        for (int i = 0; i < 2; i++) {
            int f = tid + i * 256;           // 0..511
            int r = f >> 2;                  // 0..127
            int c8 = (f & 3) * 8;            // 0,8,16,24
            cp16(stage + a * MM_ARR + r * MM_ROWB + c8 * 2,
                 srcs[a] + (size_t)(r0s[a] + r) * DM + k0 + c8);
        }
    }
    asm volatile("cp.async.commit_group;" ::: "memory");
}

__device__ __forceinline__ void tc_gemm_tile(
    const __nv_bfloat16* __restrict__ Ah, const __nv_bfloat16* __restrict__ Al,
    const __nv_bfloat16* __restrict__ Bh, const __nv_bfloat16* __restrict__ Bl,
    const float* __restrict__ bias, float* __restrict__ Y,
    int m0, int n0, char* smem)
{
    const int tid  = threadIdx.x;
    const int wid  = tid >> 5;
    const int lane = tid & 31;
    const int wm   = wid >> 1;      // 0..3 -> m offset 32*wm
    const int wn   = wid & 1;       // 0..1 -> n offset 64*wn
    const uint32_t sbase = smem_u32(smem);

    float acc[16][4];
#pragma unroll
    for (int i = 0; i < 16; i++)
#pragma unroll
        for (int j = 0; j < 4; j++) acc[i][j] = 0.f;

    // ldmatrix lane address components (within stage)
    const int la_row = lane & 15, la_kh = (lane >> 4) * 8;          // A pattern
    const int lb_j = lane & 7, lb_sel = lane >> 3;                  // B pattern
    const int lb_rowoff = (lb_sel >> 1) * 8 + lb_j;
    const int lb_kh = (lb_sel & 1) * 8;

    mm_load_chunk(Ah, Al, Bh, Bl, m0, n0, 0, sbase, tid);

    for (int c = 0; c < DM / 32; c++) {       // 24 chunks
        const uint32_t stage = sbase + (uint32_t)(c & 1) * MM_STAGE;
        if (c + 1 < DM / 32) {
            mm_load_chunk(Ah, Al, Bh, Bl, m0, n0, (c + 1) * 32,
                          sbase + (uint32_t)((c + 1) & 1) * MM_STAGE, tid);
            asm volatile("cp.async.wait_group 1;" ::: "memory");
        } else {
            asm volatile("cp.async.wait_group 0;" ::: "memory");
        }
        __syncthreads();

#pragma unroll
        for (int ks = 0; ks < 2; ks++) {
            const int k16 = ks * 16;
            uint32_t ah[2][4], al[2][4];
#pragma unroll
            for (int im = 0; im < 2; im++) {
                uint32_t ra = (uint32_t)((wm * 32 + im * 16 + la_row) * MM_ROWB
                                         + (k16 + la_kh) * 2);
                ldsm4(ah[im], stage + 0 * MM_ARR + ra);
                ldsm4(al[im], stage + 1 * MM_ARR + ra);
            }
#pragma unroll
            for (int bp = 0; bp < 4; bp++) {
                uint32_t rb = (uint32_t)((wn * 64 + bp * 16 + lb_rowoff) * MM_ROWB
                                         + (k16 + lb_kh) * 2);
                uint32_t bh[4], bl[4];
                ldsm4(bh, stage + 2 * MM_ARR + rb);
                ldsm4(bl, stage + 3 * MM_ARR + rb);
#pragma unroll
                for (int im = 0; im < 2; im++)
#pragma unroll
                    for (int fp = 0; fp < 2; fp++) {
                        float* cc = acc[im * 8 + bp * 2 + fp];
                        mma16816(cc, ah[im], bh[fp*2], bh[fp*2+1]);
                        mma16816(cc, ah[im], bl[fp*2], bl[fp*2+1]);
                        mma16816(cc, al[im], bh[fp*2], bh[fp*2+1]);
                    }
            }
        }
        __syncthreads();
    }

    // epilogue: frag layout -> Y + bias
    const int rquad = lane >> 2, cpair = (lane & 3) * 2;
#pragma unroll
    for (int im = 0; im < 2; im++)
#pragma unroll
        for (int bp = 0; bp < 4; bp++)
#pragma unroll
            for (int fp = 0; fp < 2; fp++) {
                const float* cc = acc[im * 8 + bp * 2 + fp];
                int m = m0 + wm * 32 + im * 16 + rquad;
                int n = n0 + wn * 64 + bp * 16 + fp * 8 + cpair;
                float b0 = bias[n], b1 = bias[n + 1];
                float2 o0 = make_float2(cc[0] + b0, cc[1] + b1);
                float2 o1 = make_float2(cc[2] + b0, cc[3] + b1);
                *(float2*)&Y[(size_t)m * DM + n]       = o0;
                *(float2*)&Y[(size_t)(m + 8) * DM + n] = o1;
            }
}

__global__ void __launch_bounds__(256) tc_qkv_kernel(
    const __nv_bfloat16* __restrict__ Xh, const __nv_bfloat16* __restrict__ Xl,
    const __nv_bfloat16* __restrict__ Wqh, const __nv_bfloat16* __restrict__ Wql,
    const float* __restrict__ bq, float* __restrict__ Yq,
    const __nv_bfloat16* __restrict__ Wkh, const __nv_bfloat16* __restrict__ Wkl,
    const float* __restrict__ bk, float* __restrict__ Yk,
    const __nv_bfloat16* __restrict__ Wvh, const __nv_bfloat16* __restrict__ Wvl,
    const float* __restrict__ bv, float* __restrict__ Yv)
{
    extern __shared__ char smem[];
    const __nv_bfloat16 *Wh, *Wl; const float* b; float* Y;
    if (blockIdx.z == 0)      { Wh = Wqh; Wl = Wql; b = bq; Y = Yq; }
    else if (blockIdx.z == 1) { Wh = Wkh; Wl = Wkl; b = bk; Y = Yk; }
    else                      { Wh = Wvh; Wl = Wvl; b = bv; Y = Yv; }
    tc_gemm_tile(Xh, Xl, Wh, Wl, b, Y, blockIdx.y * 128, blockIdx.x * 128, smem);
}

__global__ void __launch_bounds__(256) tc_out_kernel(
    const __nv_bfloat16* __restrict__ Ah, const __nv_bfloat16* __restrict__ Al,
    const __nv_bfloat16* __restrict__ Wh, const __nv_bfloat16* __restrict__ Wl,
    const float* __restrict__ b, float* __restrict__ Y)
{
    extern __shared__ char smem[];
    tc_gemm_tile(Ah, Al, Wh, Wl, b, Y, blockIdx.y * 128, blockIdx.x * 128, smem);
}

// ----------------------------------------------------------------------------
// Flash attention (fp32, online softmax) — unchanged from R2 (passing).
// ----------------------------------------------------------------------------
struct AttnSmem {
    float Qt[DKH][128];
    float Kt[DKH][64];
    float Vt[64][DKH];
    float S[128][65];
    float mrow[128];
    float lrow[128];
    float crow[128];
};

__global__ void __launch_bounds__(256) attn_kernel(
    const float* __restrict__ Q, const float* __restrict__ K,
    const float* __restrict__ V, float* __restrict__ CTX)
{
    extern __shared__ char smem_raw[];
    AttnSmem& sm = *reinterpret_cast<AttnSmem*>(smem_raw);

    const int tid = threadIdx.x;
    const int b = blockIdx.z, h = blockIdx.y;
    const int q0 = blockIdx.x * 128;
    const int tx = tid & 15;
    const int ty = tid >> 4;
    const float scale = 0.125f;

#pragma unroll
    for (int i = 0; i < 8; i++) {
        int f = tid + i * 256;
        int qr = f >> 4;
        int c4 = (f & 15) * 4;
        float4 v = *(const float4*)&Q[(b * SEQ + q0 + qr) * DM + h * DKH + c4];
        sm.Qt[c4 + 0][qr] = v.x * scale;
        sm.Qt[c4 + 1][qr] = v.y * scale;
        sm.Qt[c4 + 2][qr] = v.z * scale;
        sm.Qt[c4 + 3][qr] = v.w * scale;
    }
    if (tid < 128) {
        sm.mrow[tid] = -INFINITY;
        sm.lrow[tid] = 0.f;
    }

    float oacc[8][4];
#pragma unroll
    for (int i = 0; i < 8; i++)
#pragma unroll
        for (int j = 0; j < 4; j++) oacc[i][j] = 0.f;

    __syncthreads();

    for (int kt = 0; kt < SEQ / 64; kt++) {
        const int sk0 = kt * 64;
#pragma unroll
        for (int i = 0; i < 4; i++) {
            int f = tid + i * 256;
            int r = f >> 4;
            int c4 = (f & 15) * 4;
            int g = (b * SEQ + sk0 + r) * DM + h * DKH + c4;
            float4 kv = *(const float4*)&K[g];
            sm.Kt[c4 + 0][r] = kv.x;
            sm.Kt[c4 + 1][r] = kv.y;
            sm.Kt[c4 + 2][r] = kv.z;
            sm.Kt[c4 + 3][r] = kv.w;
            *(float4*)&sm.Vt[r][c4] = *(const float4*)&V[g];
        }
        __syncthreads();

        float sreg[8][4];
#pragma unroll
        for (int i = 0; i < 8; i++)
#pragma unroll
            for (int j = 0; j < 4; j++) sreg[i][j] = 0.f;

#pragma unroll 8
        for (int d = 0; d < DKH; d++) {
            float4 qa0 = *(const float4*)&sm.Qt[d][ty * 8];
            float4 qa1 = *(const float4*)&sm.Qt[d][ty * 8 + 4];
            float4 kb  = *(const float4*)&sm.Kt[d][tx * 4];
            float qq[8] = {qa0.x, qa0.y, qa0.z, qa0.w, qa1.x, qa1.y, qa1.z, qa1.w};
            float kk[4] = {kb.x, kb.y, kb.z, kb.w};
#pragma unroll
            for (int i = 0; i < 8; i++)
#pragma unroll
                for (int j = 0; j < 4; j++)
                    sreg[i][j] = fmaf(qq[i], kk[j], sreg[i][j]);
        }
#pragma unroll
        for (int i = 0; i < 8; i++)
#pragma unroll
            for (int j = 0; j < 4; j++)
                sm.S[ty * 8 + i][tx * 4 + j] = sreg[i][j];
        __syncthreads();

        {
            int q = tid >> 1;
            int half = tid & 1;
            int c0 = half * 32;
            float pm = -INFINITY;
#pragma unroll 8
            for (int c = 0; c < 32; c++) pm = fmaxf(pm, sm.S[q][c0 + c]);
            pm = fmaxf(pm, __shfl_xor_sync(0xffffffffu, pm, 1));
            float oldm = sm.mrow[q];
            float newm = fmaxf(oldm, pm);
            float corr = __expf(oldm - newm);
            float ps = 0.f;
#pragma unroll 8
            for (int c = 0; c < 32; c++) {
                float p = __expf(sm.S[q][c0 + c] - newm);
                sm.S[q][c0 + c] = p;
                ps += p;
            }
            ps += __shfl_xor_sync(0xffffffffu, ps, 1);
            if (half == 0) {
                sm.mrow[q] = newm;
                sm.lrow[q] = sm.lrow[q] * corr + ps;
                sm.crow[q] = corr;
            }
        }
        __syncthreads();

        float cf[8];
#pragma unroll
        for (int i = 0; i < 8; i++) cf[i] = sm.crow[ty * 8 + i];
#pragma unroll
        for (int i = 0; i < 8; i++)
#pragma unroll
            for (int j = 0; j < 4; j++) oacc[i][j] *= cf[i];

#pragma unroll 8
        for (int k = 0; k < 64; k++) {
            float4 v4 = *(const float4*)&sm.Vt[k][tx * 4];
            float vv[4] = {v4.x, v4.y, v4.z, v4.w};
#pragma unroll
            for (int i = 0; i < 8; i++) {
                float p = sm.S[ty * 8 + i][k];
#pragma unroll
                for (int j = 0; j < 4; j++)
                    oacc[i][j] = fmaf(p, vv[j], oacc[i][j]);
            }
        }
        __syncthreads();
    }

#pragma unroll
    for (int i = 0; i < 8; i++) {
        int q = ty * 8 + i;
        float inv = 1.0f / sm.lrow[q];
        float4 o;
        o.x = oacc[i][0] * inv;
        o.y = oacc[i][1] * inv;
        o.z = oacc[i][2] * inv;
        o.w = oacc[i][3] * inv;
        *(float4*)&CTX[(b * SEQ + q0 + q) * DM + h * DKH + tx * 4] = o;
    }
}

// ----------------------------------------------------------------------------
// Launch
// ----------------------------------------------------------------------------
extern "C" void kernel_launch(void* const* d_in, const int* in_sizes, int n_in,
                              void* d_out, int out_size)
{
    (void)in_sizes; (void)n_in; (void)out_size;
    const float* x   = (const float*)d_in[0];
    const float* w_q = (const float*)d_in[1];
    const float* b_q = (const float*)d_in[2];
    const float* w_k = (const float*)d_in[3];
    const float* b_k = (const float*)d_in[4];
    const float* w_v = (const float*)d_in[5];
    const float* b_v = (const float*)d_in[6];
    const float* w_o = (const float*)d_in[7];
    const float* b_o = (const float*)d_in[8];
    float* out = (float*)d_out;

    float *q, *k, *v, *ctx;
    cudaGetSymbolAddress((void**)&q,   g_q);
    cudaGetSymbolAddress((void**)&k,   g_k);
    cudaGetSymbolAddress((void**)&v,   g_v);
    cudaGetSymbolAddress((void**)&ctx, g_ctx);

    __nv_bfloat16 *xh, *xl, *ch, *cl;
    __nv_bfloat16 *wqh, *wql, *wkh, *wkl, *wvh, *wvl, *woh, *wol;
    cudaGetSymbolAddress((void**)&xh, g_xh);   cudaGetSymbolAddress((void**)&xl, g_xl);
    cudaGetSymbolAddress((void**)&ch, g_ch);   cudaGetSymbolAddress((void**)&cl, g_cl);
    cudaGetSymbolAddress((void**)&wqh, g_wqh); cudaGetSymbolAddress((void**)&wql, g_wql);
    cudaGetSymbolAddress((void**)&wkh, g_wkh); cudaGetSymbolAddress((void**)&wkl, g_wkl);
    cudaGetSymbolAddress((void**)&wvh, g_wvh); cudaGetSymbolAddress((void**)&wvl, g_wvl);
    cudaGetSymbolAddress((void**)&woh, g_woh); cudaGetSymbolAddress((void**)&wol, g_wol);

    const int NX4 = MTOK * DM / 4;
    const int NW4 = DM * DM / 4;
    cvt_hilo_kernel<<<(NX4 + 255) / 256, 256>>>(x, xh, xl, NX4);
    dim3 gw((NW4 + 255) / 256, 4);
    cvt_w4_kernel<<<gw, 256>>>(w_q, wqh, wql, w_k, wkh, wkl,
                               w_v, wvh, wvl, w_o, woh, wol, NW4);

    cudaFuncSetAttribute(tc_qkv_kernel,
                         cudaFuncAttributeMaxDynamicSharedMemorySize, MM_SMEM);
    cudaFuncSetAttribute(tc_out_kernel,
                         cudaFuncAttributeMaxDynamicSharedMemorySize, MM_SMEM);

    dim3 gqkv(DM / 128, MTOK / 128, 3);   // (6, 32, 3)
    tc_qkv_kernel<<<gqkv, 256, MM_SMEM>>>(
        xh, xl, wqh, wql, b_q, q, wkh, wkl, b_k, k, wvh, wvl, b_v, v);

    cudaFuncSetAttribute(attn_kernel,
                         cudaFuncAttributeMaxDynamicSharedMemorySize,
                         (int)sizeof(AttnSmem));
    attn_kernel<<<dim3(SEQ / 128, NH, BATCH), 256, sizeof(AttnSmem)>>>(q, k, v, ctx);

    cvt_hilo_kernel<<<(NX4 + 255) / 256, 256>>>(ctx, ch, cl, NX4);

    dim3 go(DM / 128, MTOK / 128);        // (6, 32)
    tc_out_kernel<<<go, 256, MM_SMEM>>>(ch, cl, woh, wol, b_o, out);
}

// round 6
// speedup vs baseline: 2.8444x; 2.1881x over previous
#include <cuda_runtime.h>
#include <cuda_bf16.h>
#include <math.h>
#include <stdint.h>

// ============================================================================
// MultiHeadAttention: x[2,2048,768] -> out[2,2048,768]
// R6: everything on mma.sync.m16n8k16 bf16 (3-way precision split, fp32 acc).
//  - qkv GEMM writes Q(pre-scaled)/K/V as bf16 hi/lo directly
//  - flash attention on tensor cores (frag-reuse softmax, ldmatrix.trans V)
//  - out GEMM 3-split -> fp32
// ============================================================================

#define BATCH 2
#define SEQ   2048
#define DM    768
#define NH    12
#define DKH   64
#define MTOK  (BATCH*SEQ)   // 4096

// bf16 hi/lo scratch
__device__ __nv_bfloat16 g_xh[MTOK*DM],  g_xl[MTOK*DM];
__device__ __nv_bfloat16 g_qh[MTOK*DM],  g_ql[MTOK*DM];
__device__ __nv_bfloat16 g_kh[MTOK*DM],  g_kl[MTOK*DM];
__device__ __nv_bfloat16 g_vh[MTOK*DM],  g_vl[MTOK*DM];
__device__ __nv_bfloat16 g_ch[MTOK*DM],  g_cl[MTOK*DM];
__device__ __nv_bfloat16 g_wqh[DM*DM], g_wql[DM*DM];
__device__ __nv_bfloat16 g_wkh[DM*DM], g_wkl[DM*DM];
__device__ __nv_bfloat16 g_wvh[DM*DM], g_wvl[DM*DM];
__device__ __nv_bfloat16 g_woh[DM*DM], g_wol[DM*DM];

// ----------------------------------------------------------------------------
// small helpers
// ----------------------------------------------------------------------------
__device__ __forceinline__ uint32_t smem_u32(const void* p) {
    uint32_t a;
    asm("{ .reg .u64 t; cvta.to.shared.u64 t, %1; cvt.u32.u64 %0, t; }"
        : "=r"(a) : "l"(p));
    return a;
}
__device__ __forceinline__ void cp16(uint32_t dst, const void* src) {
    asm volatile("cp.async.cg.shared.global [%0], [%1], 16;"
                 :: "r"(dst), "l"(src) : "memory");
}
__device__ __forceinline__ void ldsm4(uint32_t* r, uint32_t addr) {
    asm volatile("ldmatrix.sync.aligned.m8n8.x4.shared.b16 {%0,%1,%2,%3}, [%4];"
                 : "=r"(r[0]), "=r"(r[1]), "=r"(r[2]), "=r"(r[3]) : "r"(addr));
}
__device__ __forceinline__ void ldsm4t(uint32_t* r, uint32_t addr) {
    asm volatile("ldmatrix.sync.aligned.m8n8.x4.trans.shared.b16 {%0,%1,%2,%3}, [%4];"
                 : "=r"(r[0]), "=r"(r[1]), "=r"(r[2]), "=r"(r[3]) : "r"(addr));
}
__device__ __forceinline__ void mma16816(float* c, const uint32_t* a,
                                         uint32_t b0, uint32_t b1) {
    asm volatile(
        "mma.sync.aligned.m16n8k16.row.col.f32.bf16.bf16.f32 "
        "{%0,%1,%2,%3}, {%4,%5,%6,%7}, {%8,%9}, {%0,%1,%2,%3};"
        : "+f"(c[0]), "+f"(c[1]), "+f"(c[2]), "+f"(c[3])
        : "r"(a[0]), "r"(a[1]), "r"(a[2]), "r"(a[3]), "r"(b0), "r"(b1));
}
__device__ __forceinline__ uint32_t pack_hi(float a, float b) {
    __nv_bfloat162 t = __floats2bfloat162_rn(a, b);
    return *(uint32_t*)&t;
}
__device__ __forceinline__ uint32_t pack_lo(float a, float b, uint32_t hi) {
    __nv_bfloat162 h = *(__nv_bfloat162*)&hi;
    __nv_bfloat162 t = __floats2bfloat162_rn(a - __bfloat162float(h.x),
                                             b - __bfloat162float(h.y));
    return *(uint32_t*)&t;
}

// ----------------------------------------------------------------------------
// fp32 -> bf16 hi/lo split
// ----------------------------------------------------------------------------
__device__ __forceinline__ void cvt_hilo_body(
    const float* __restrict__ s, __nv_bfloat16* __restrict__ hi,
    __nv_bfloat16* __restrict__ lo, int n4, int i)
{
    if (i >= n4) return;
    float4 v = ((const float4*)s)[i];
    uint32_t h0 = pack_hi(v.x, v.y), h1 = pack_hi(v.z, v.w);
    uint32_t l0 = pack_lo(v.x, v.y, h0), l1 = pack_lo(v.z, v.w, h1);
    ((uint32_t*)hi)[2*i]   = h0;
    ((uint32_t*)hi)[2*i+1] = h1;
    ((uint32_t*)lo)[2*i]   = l0;
    ((uint32_t*)lo)[2*i+1] = l1;
}

__global__ void __launch_bounds__(256) cvt_hilo_kernel(
    const float* __restrict__ s, __nv_bfloat16* __restrict__ hi,
    __nv_bfloat16* __restrict__ lo, int n4)
{
    cvt_hilo_body(s, hi, lo, n4, blockIdx.x * blockDim.x + threadIdx.x);
}

__global__ void __launch_bounds__(256) cvt_w4_kernel(
    const float* __restrict__ s0, __nv_bfloat16* __restrict__ h0, __nv_bfloat16* __restrict__ l0,
    const float* __restrict__ s1, __nv_bfloat16* __restrict__ h1, __nv_bfloat16* __restrict__ l1,
    const float* __restrict__ s2, __nv_bfloat16* __restrict__ h2, __nv_bfloat16* __restrict__ l2,
    const float* __restrict__ s3, __nv_bfloat16* __restrict__ h3, __nv_bfloat16* __restrict__ l3,
    int n4)
{
    const float* s; __nv_bfloat16 *h, *l;
    switch (blockIdx.y) {
        case 0: s = s0; h = h0; l = l0; break;
        case 1: s = s1; h = h1; l = l1; break;
        case 2: s = s2; h = h2; l = l2; break;
        default: s = s3; h = h3; l = l3; break;
    }
    cvt_hilo_body(s, h, l, n4, blockIdx.x * blockDim.x + threadIdx.x);
}

// ----------------------------------------------------------------------------
// mma.sync bf16 3-split GEMM (from R5, passing). Template epilogue:
// BF16OUT=false -> fp32 Y + bias;  BF16OUT=true -> bf16 hi/lo of scale*(Y+bias)
// ----------------------------------------------------------------------------
#define MM_ROWB   80
#define MM_ARR    10240
#define MM_STAGE  (4*MM_ARR)
#define MM_SMEM   (2*MM_STAGE)

__device__ __forceinline__ void mm_load_chunk(
    const __nv_bfloat16* __restrict__ Ah, const __nv_bfloat16* __restrict__ Al,
    const __nv_bfloat16* __restrict__ Bh, const __nv_bfloat16* __restrict__ Bl,
    int m0, int n0, int k0, uint32_t stage, int tid)
{
    const __nv_bfloat16* srcs[4] = {Ah, Al, Bh, Bl};
    const int r0s[4] = {m0, m0, n0, n0};
#pragma unroll
    for (int a = 0; a < 4; a++) {
#pragma unroll
        for (int i = 0; i < 2; i++) {
            int f = tid + i * 256;
            int r = f >> 2;
            int c8 = (f & 3) * 8;
            cp16(stage + a * MM_ARR + r * MM_ROWB + c8 * 2,
                 srcs[a] + (size_t)(r0s[a] + r) * DM + k0 + c8);
        }
    }
    asm volatile("cp.async.commit_group;" ::: "memory");
}

template<bool BF16OUT>
__device__ __forceinline__ void tc_gemm_tile(
    const __nv_bfloat16* __restrict__ Ah, const __nv_bfloat16* __restrict__ Al,
    const __nv_bfloat16* __restrict__ Bh, const __nv_bfloat16* __restrict__ Bl,
    const float* __restrict__ bias, float* __restrict__ Yf,
    __nv_bfloat16* __restrict__ Yh, __nv_bfloat16* __restrict__ Yl, float scale,
    int m0, int n0, char* smem)
{
    const int tid  = threadIdx.x;
    const int wid  = tid >> 5;
    const int lane = tid & 31;
    const int wm   = wid >> 1;
    const int wn   = wid & 1;
    const uint32_t sbase = smem_u32(smem);

    float acc[16][4];
#pragma unroll
    for (int i = 0; i < 16; i++)
#pragma unroll
        for (int j = 0; j < 4; j++) acc[i][j] = 0.f;

    const int la_row = lane & 15, la_kh = (lane >> 4) * 8;
    const int lb_j = lane & 7, lb_sel = lane >> 3;
    const int lb_rowoff = (lb_sel >> 1) * 8 + lb_j;
    const int lb_kh = (lb_sel & 1) * 8;

    mm_load_chunk(Ah, Al, Bh, Bl, m0, n0, 0, sbase, tid);

    for (int c = 0; c < DM / 32; c++) {
        const uint32_t stage = sbase + (uint32_t)(c & 1) * MM_STAGE;
        if (c + 1 < DM / 32) {
            mm_load_chunk(Ah, Al, Bh, Bl, m0, n0, (c + 1) * 32,
                          sbase + (uint32_t)((c + 1) & 1) * MM_STAGE, tid);
            asm volatile("cp.async.wait_group 1;" ::: "memory");
        } else {
            asm volatile("cp.async.wait_group 0;" ::: "memory");
        }
        __syncthreads();

#pragma unroll
        for (int ks = 0; ks < 2; ks++) {
            const int k16 = ks * 16;
            uint32_t ah[2][4], al[2][4];
#pragma unroll
            for (int im = 0; im < 2; im++) {
                uint32_t ra = (uint32_t)((wm * 32 + im * 16 + la_row) * MM_ROWB
                                         + (k16 + la_kh) * 2);
                ldsm4(ah[im], stage + 0 * MM_ARR + ra);
                ldsm4(al[im], stage + 1 * MM_ARR + ra);
            }
#pragma unroll
            for (int bp = 0; bp < 4; bp++) {
                uint32_t rb = (uint32_t)((wn * 64 + bp * 16 + lb_rowoff) * MM_ROWB
                                         + (k16 + lb_kh) * 2);
                uint32_t bh[4], bl[4];
                ldsm4(bh, stage + 2 * MM_ARR + rb);
                ldsm4(bl, stage + 3 * MM_ARR + rb);
#pragma unroll
                for (int im = 0; im < 2; im++)
#pragma unroll
                    for (int fp = 0; fp < 2; fp++) {
                        float* cc = acc[im * 8 + bp * 2 + fp];
                        mma16816(cc, ah[im], bh[fp*2], bh[fp*2+1]);
                        mma16816(cc, ah[im], bl[fp*2], bl[fp*2+1]);
                        mma16816(cc, al[im], bh[fp*2], bh[fp*2+1]);
                    }
            }
        }
        __syncthreads();
    }

    const int rquad = lane >> 2, cpair = (lane & 3) * 2;
#pragma unroll
    for (int im = 0; im < 2; im++)
#pragma unroll
        for (int bp = 0; bp < 4; bp++)
#pragma unroll
            for (int fp = 0; fp < 2; fp++) {
                const float* cc = acc[im * 8 + bp * 2 + fp];
                int m = m0 + wm * 32 + im * 16 + rquad;
                int n = n0 + wn * 64 + bp * 16 + fp * 8 + cpair;
                float b0 = bias[n], b1 = bias[n + 1];
                if (BF16OUT) {
                    float e0 = (cc[0] + b0) * scale, e1 = (cc[1] + b1) * scale;
                    float e2 = (cc[2] + b0) * scale, e3 = (cc[3] + b1) * scale;
                    uint32_t h0 = pack_hi(e0, e1), h1 = pack_hi(e2, e3);
                    *(uint32_t*)&Yh[(size_t)m * DM + n]       = h0;
                    *(uint32_t*)&Yl[(size_t)m * DM + n]       = pack_lo(e0, e1, h0);
                    *(uint32_t*)&Yh[(size_t)(m + 8) * DM + n] = h1;
                    *(uint32_t*)&Yl[(size_t)(m + 8) * DM + n] = pack_lo(e2, e3, h1);
                } else {
                    float2 o0 = make_float2(cc[0] + b0, cc[1] + b1);
                    float2 o1 = make_float2(cc[2] + b0, cc[3] + b1);
                    *(float2*)&Yf[(size_t)m * DM + n]       = o0;
                    *(float2*)&Yf[(size_t)(m + 8) * DM + n] = o1;
                }
            }
}

__global__ void __launch_bounds__(256) tc_qkv_kernel(
    const __nv_bfloat16* __restrict__ Xh, const __nv_bfloat16* __restrict__ Xl,
    const __nv_bfloat16* __restrict__ Wqh, const __nv_bfloat16* __restrict__ Wql,
    const float* __restrict__ bq,
    __nv_bfloat16* __restrict__ Qh, __nv_bfloat16* __restrict__ Ql,
    const __nv_bfloat16* __restrict__ Wkh, const __nv_bfloat16* __restrict__ Wkl,
    const float* __restrict__ bk,
    __nv_bfloat16* __restrict__ Kh, __nv_bfloat16* __restrict__ Kl,
    const __nv_bfloat16* __restrict__ Wvh, const __nv_bfloat16* __restrict__ Wvl,
    const float* __restrict__ bv,
    __nv_bfloat16* __restrict__ Vh, __nv_bfloat16* __restrict__ Vl)
{
    extern __shared__ char smem[];
    const __nv_bfloat16 *Wh, *Wl; const float* b;
    __nv_bfloat16 *Yh, *Yl; float scale;
    if (blockIdx.z == 0)      { Wh = Wqh; Wl = Wql; b = bq; Yh = Qh; Yl = Ql; scale = 0.125f; }
    else if (blockIdx.z == 1) { Wh = Wkh; Wl = Wkl; b = bk; Yh = Kh; Yl = Kl; scale = 1.f; }
    else                      { Wh = Wvh; Wl = Wvl; b = bv; Yh = Vh; Yl = Vl; scale = 1.f; }
    tc_gemm_tile<true>(Xh, Xl, Wh, Wl, b, nullptr, Yh, Yl, scale,
                       blockIdx.y * 128, blockIdx.x * 128, smem);
}

__global__ void __launch_bounds__(256) tc_out_kernel(
    const __nv_bfloat16* __restrict__ Ah, const __nv_bfloat16* __restrict__ Al,
    const __nv_bfloat16* __restrict__ Wh, const __nv_bfloat16* __restrict__ Wl,
    const float* __restrict__ b, float* __restrict__ Y)
{
    extern __shared__ char smem[];
    tc_gemm_tile<false>(Ah, Al, Wh, Wl, b, Y, nullptr, nullptr, 1.f,
                        blockIdx.y * 128, blockIdx.x * 128, smem);
}

// ----------------------------------------------------------------------------
// Flash attention on mma.sync. CTA: 128 queries x one (b,h); 8 warps x 16 rows.
// K-tile 128 keys, K/V hi/lo double-buffered via cp.async. QK^T 3-split,
// softmax in registers, P repacked as A-frags, PV 3-split with ldmatrix.trans V.
// smem rows padded to 72 bf16 (144B) -> conflict-free ldmatrix.
// ----------------------------------------------------------------------------
#define AT_ROWB 144
#define AT_ARR  (128*AT_ROWB)            // 18432
#define AT_SQ   0
#define AT_ST0  (2*AT_ARR)
#define AT_STSZ (4*AT_ARR)
#define AT_SMEM (2*AT_ARR + 2*AT_STSZ)   // 184320

__device__ __forceinline__ void at_load_arr(
    const __nv_bfloat16* __restrict__ src, uint32_t dst, int tok0, int h, int tid)
{
#pragma unroll
    for (int i = 0; i < 4; i++) {
        int f = tid + i * 256;        // 0..1023
        int r = f >> 3, c = f & 7;
        cp16(dst + r * AT_ROWB + c * 16,
             src + (size_t)(tok0 + r) * DM + h * DKH + c * 8);
    }
}

__global__ void __launch_bounds__(256) attn_mma_kernel(
    const __nv_bfloat16* __restrict__ Qh, const __nv_bfloat16* __restrict__ Ql,
    const __nv_bfloat16* __restrict__ Kh, const __nv_bfloat16* __restrict__ Kl,
    const __nv_bfloat16* __restrict__ Vh, const __nv_bfloat16* __restrict__ Vl,
    __nv_bfloat16* __restrict__ Ch, __nv_bfloat16* __restrict__ Cl)
{
    extern __shared__ char smem[];
    const uint32_t sb = smem_u32(smem);
    const int tid = threadIdx.x, wid = tid >> 5, lane = tid & 31;
    const int b = blockIdx.z, h = blockIdx.y, q0 = blockIdx.x * 128;
    const int tokQ = b * SEQ + q0, tokK = b * SEQ;

    // Q tiles (group 0)
    at_load_arr(Qh, sb + AT_SQ,          tokQ, h, tid);
    at_load_arr(Ql, sb + AT_SQ + AT_ARR, tokQ, h, tid);
    asm volatile("cp.async.commit_group;" ::: "memory");
    // stage 0 K/V (group 1)
    {
        uint32_t st = sb + AT_ST0;
        at_load_arr(Kh, st,              tokK, h, tid);
        at_load_arr(Kl, st + AT_ARR,     tokK, h, tid);
        at_load_arr(Vh, st + 2*AT_ARR,   tokK, h, tid);
        at_load_arr(Vl, st + 3*AT_ARR,   tokK, h, tid);
        asm volatile("cp.async.commit_group;" ::: "memory");
    }
    asm volatile("cp.async.wait_group 1;" ::: "memory");   // Q ready
    __syncthreads();

    // Q fragments (held across all tiles)
    const int la_row = lane & 15, la_k = (lane >> 4) * 8;
    uint32_t qfh[4][4], qfl[4][4];
#pragma unroll
    for (int kc = 0; kc < 4; kc++) {
        uint32_t a = sb + AT_SQ + (uint32_t)((wid * 16 + la_row) * AT_ROWB
                                             + (kc * 16 + la_k) * 2);
        ldsm4(qfh[kc], a);
        ldsm4(qfl[kc], a + AT_ARR);
    }

    float of[8][4];
#pragma unroll
    for (int i = 0; i < 8; i++)
#pragma unroll
        for (int j = 0; j < 4; j++) of[i][j] = 0.f;
    float m0 = -INFINITY, m1 = -INFINITY, l0 = 0.f, l1 = 0.f;

    const int lb_j = lane & 7, lb_sel = lane >> 3;
    const int lb_row = (lb_sel >> 1) * 8 + lb_j;
    const int lb_k = (lb_sel & 1) * 8;

    for (int kt = 0; kt < 16; kt++) {
        const uint32_t stg = sb + AT_ST0 + (uint32_t)(kt & 1) * AT_STSZ;
        if (kt < 15) {
            uint32_t nst = sb + AT_ST0 + (uint32_t)((kt + 1) & 1) * AT_STSZ;
            int tk = tokK + (kt + 1) * 128;
            at_load_arr(Kh, nst,            tk, h, tid);
            at_load_arr(Kl, nst + AT_ARR,   tk, h, tid);
            at_load_arr(Vh, nst + 2*AT_ARR, tk, h, tid);
            at_load_arr(Vl, nst + 3*AT_ARR, tk, h, tid);
            asm volatile("cp.async.commit_group;" ::: "memory");
            asm volatile("cp.async.wait_group 1;" ::: "memory");
        } else {
            asm volatile("cp.async.wait_group 0;" ::: "memory");
        }
        __syncthreads();

        // ---- S = Q K^T (3-split), warp rows wid*16..+15, keys 0..127
        float sf[16][4];
#pragma unroll
        for (int kn = 0; kn < 8; kn++) {
#pragma unroll
            for (int nb = 0; nb < 2; nb++)
#pragma unroll
                for (int j = 0; j < 4; j++) sf[2*kn+nb][j] = 0.f;
#pragma unroll
            for (int kc = 0; kc < 4; kc++) {
                uint32_t ka = stg + (uint32_t)((kn * 16 + lb_row) * AT_ROWB
                                               + (kc * 16 + lb_k) * 2);
                uint32_t bh4[4], bl4[4];
                ldsm4(bh4, ka);
                ldsm4(bl4, ka + AT_ARR);
#pragma unroll
                for (int nb = 0; nb < 2; nb++) {
                    mma16816(sf[2*kn+nb], qfh[kc], bh4[nb*2], bh4[nb*2+1]);
                    mma16816(sf[2*kn+nb], qfh[kc], bl4[nb*2], bl4[nb*2+1]);
                    mma16816(sf[2*kn+nb], qfl[kc], bh4[nb*2], bh4[nb*2+1]);
                }
            }
        }

        // ---- online softmax (rows rquad and rquad+8; 4 lanes per row)
        float mx0 = -INFINITY, mx1 = -INFINITY;
#pragma unroll
        for (int j = 0; j < 16; j++) {
            mx0 = fmaxf(mx0, fmaxf(sf[j][0], sf[j][1]));
            mx1 = fmaxf(mx1, fmaxf(sf[j][2], sf[j][3]));
        }
        mx0 = fmaxf(mx0, __shfl_xor_sync(0xffffffffu, mx0, 1));
        mx0 = fmaxf(mx0, __shfl_xor_sync(0xffffffffu, mx0, 2));
        mx1 = fmaxf(mx1, __shfl_xor_sync(0xffffffffu, mx1, 1));
        mx1 = fmaxf(mx1, __shfl_xor_sync(0xffffffffu, mx1, 2));
        const float m0n = fmaxf(m0, mx0), m1n = fmaxf(m1, mx1);
        const float c0 = __expf(m0 - m0n), c1 = __expf(m1 - m1n);
#pragma unroll
        for (int j = 0; j < 8; j++) {
            of[j][0] *= c0; of[j][1] *= c0;
            of[j][2] *= c1; of[j][3] *= c1;
        }
        float rs0 = 0.f, rs1 = 0.f;
#pragma unroll
        for (int j = 0; j < 16; j++) {
            sf[j][0] = __expf(sf[j][0] - m0n); rs0 += sf[j][0];
            sf[j][1] = __expf(sf[j][1] - m0n); rs0 += sf[j][1];
            sf[j][2] = __expf(sf[j][2] - m1n); rs1 += sf[j][2];
            sf[j][3] = __expf(sf[j][3] - m1n); rs1 += sf[j][3];
        }
        rs0 += __shfl_xor_sync(0xffffffffu, rs0, 1);
        rs0 += __shfl_xor_sync(0xffffffffu, rs0, 2);
        rs1 += __shfl_xor_sync(0xffffffffu, rs1, 1);
        rs1 += __shfl_xor_sync(0xffffffffu, rs1, 2);
        l0 = l0 * c0 + rs0;
        l1 = l1 * c1 + rs1;
        m0 = m0n; m1 = m1n;

        // ---- O += P V (3-split: PhVh + PlVh + PhVl)
#pragma unroll
        for (int kc = 0; kc < 8; kc++) {
            uint32_t ph[4], pl[4];
            ph[0] = pack_hi(sf[2*kc][0],   sf[2*kc][1]);
            ph[1] = pack_hi(sf[2*kc][2],   sf[2*kc][3]);
            ph[2] = pack_hi(sf[2*kc+1][0], sf[2*kc+1][1]);
            ph[3] = pack_hi(sf[2*kc+1][2], sf[2*kc+1][3]);
            pl[0] = pack_lo(sf[2*kc][0],   sf[2*kc][1],   ph[0]);
            pl[1] = pack_lo(sf[2*kc][2],   sf[2*kc][3],   ph[1]);
            pl[2] = pack_lo(sf[2*kc+1][0], sf[2*kc+1][1], ph[2]);
            pl[3] = pack_lo(sf[2*kc+1][2], sf[2*kc+1][3], ph[3]);
#pragma unroll
            for (int dn = 0; dn < 4; dn++) {
                uint32_t va = stg + 2*AT_ARR
                            + (uint32_t)((kc * 16 + la_row) * AT_ROWB
                                         + (dn * 16 + la_k) * 2);
                uint32_t vh4[4], vl4[4];
                ldsm4t(vh4, va);
                ldsm4t(vl4, va + AT_ARR);
#pragma unroll
                for (int db = 0; db < 2; db++) {
                    float* o = of[dn * 2 + db];
                    mma16816(o, ph, vh4[db*2], vh4[db*2+1]);
                    mma16816(o, pl, vh4[db*2], vh4[db*2+1]);
                    mma16816(o, ph, vl4[db*2], vl4[db*2+1]);
                }
            }
        }
        __syncthreads();
    }

    // ---- epilogue: O/l -> ctx bf16 hi/lo
    const float i0 = 1.f / l0, i1 = 1.f / l1;
    const int rquad = lane >> 2, cpair = (lane & 3) * 2;
    const int tok = tokQ + wid * 16 + rquad;
#pragma unroll
    for (int j = 0; j < 8; j++) {
        int col = h * DKH + j * 8 + cpair;
        float e0 = of[j][0] * i0, e1 = of[j][1] * i0;
        float e2 = of[j][2] * i1, e3 = of[j][3] * i1;
        uint32_t h0 = pack_hi(e0, e1), h1 = pack_hi(e2, e3);
        *(uint32_t*)&Ch[(size_t)tok * DM + col]       = h0;
        *(uint32_t*)&Cl[(size_t)tok * DM + col]       = pack_lo(e0, e1, h0);
        *(uint32_t*)&Ch[(size_t)(tok + 8) * DM + col] = h1;
        *(uint32_t*)&Cl[(size_t)(tok + 8) * DM + col] = pack_lo(e2, e3, h1);
    }
}

// ----------------------------------------------------------------------------
// Launch
// ----------------------------------------------------------------------------
extern "C" void kernel_launch(void* const* d_in, const int* in_sizes, int n_in,
                              void* d_out, int out_size)
{
    (void)in_sizes; (void)n_in; (void)out_size;
    const float* x   = (const float*)d_in[0];
    const float* w_q = (const float*)d_in[1];
    const float* b_q = (const float*)d_in[2];
    const float* w_k = (const float*)d_in[3];
    const float* b_k = (const float*)d_in[4];
    const float* w_v = (const float*)d_in[5];
    const float* b_v = (const float*)d_in[6];
    const float* w_o = (const float*)d_in[7];
    const float* b_o = (const float*)d_in[8];
    float* out = (float*)d_out;

    __nv_bfloat16 *xh, *xl, *qh, *ql, *kh, *kl, *vh, *vl, *ch, *cl;
    __nv_bfloat16 *wqh, *wql, *wkh, *wkl, *wvh, *wvl, *woh, *wol;
    cudaGetSymbolAddress((void**)&xh, g_xh);   cudaGetSymbolAddress((void**)&xl, g_xl);
    cudaGetSymbolAddress((void**)&qh, g_qh);   cudaGetSymbolAddress((void**)&ql, g_ql);
    cudaGetSymbolAddress((void**)&kh, g_kh);   cudaGetSymbolAddress((void**)&kl, g_kl);
    cudaGetSymbolAddress((void**)&vh, g_vh);   cudaGetSymbolAddress((void**)&vl, g_vl);
    cudaGetSymbolAddress((void**)&ch, g_ch);   cudaGetSymbolAddress((void**)&cl, g_cl);
    cudaGetSymbolAddress((void**)&wqh, g_wqh); cudaGetSymbolAddress((void**)&wql, g_wql);
    cudaGetSymbolAddress((void**)&wkh, g_wkh); cudaGetSymbolAddress((void**)&wkl, g_wkl);
    cudaGetSymbolAddress((void**)&wvh, g_wvh); cudaGetSymbolAddress((void**)&wvl, g_wvl);
    cudaGetSymbolAddress((void**)&woh, g_woh); cudaGetSymbolAddress((void**)&wol, g_wol);

    const int NX4 = MTOK * DM / 4;
    const int NW4 = DM * DM / 4;
    cvt_hilo_kernel<<<(NX4 + 255) / 256, 256>>>(x, xh, xl, NX4);
    dim3 gw((NW4 + 255) / 256, 4);
    cvt_w4_kernel<<<gw, 256>>>(w_q, wqh, wql, w_k, wkh, wkl,
                               w_v, wvh, wvl, w_o, woh, wol, NW4);

    cudaFuncSetAttribute(tc_qkv_kernel,
                         cudaFuncAttributeMaxDynamicSharedMemorySize, MM_SMEM);
    cudaFuncSetAttribute(tc_out_kernel,
                         cudaFuncAttributeMaxDynamicSharedMemorySize, MM_SMEM);
    cudaFuncSetAttribute(attn_mma_kernel,
                         cudaFuncAttributeMaxDynamicSharedMemorySize, AT_SMEM);

    dim3 gqkv(DM / 128, MTOK / 128, 3);
    tc_qkv_kernel<<<gqkv, 256, MM_SMEM>>>(
        xh, xl, wqh, wql, b_q, qh, ql, wkh, wkl, b_k, kh, kl,
        wvh, wvl, b_v, vh, vl);

    attn_mma_kernel<<<dim3(SEQ / 128, NH, BATCH), 256, AT_SMEM>>>(
        qh, ql, kh, kl, vh, vl, ch, cl);

    dim3 go(DM / 128, MTOK / 128);
    tc_out_kernel<<<go, 256, MM_SMEM>>>(ch, cl, woh, wol, b_o, out);
}

// round 7
// speedup vs baseline: 2.8816x; 1.0131x over previous
#include <cuda_runtime.h>
#include <cuda_bf16.h>
#include <math.h>
#include <stdint.h>

// ============================================================================
// MultiHeadAttention: x[2,2048,768] -> out[2,2048,768]
// R7: attention reworked for 2 CTAs/SM: K-tile 64 (smem 184->108KB),
// Q-frags reloaded from smem (regs 182->~110), __launch_bounds__(256,2).
// GEMMs unchanged from R6 (passing, mma.sync 3-split).
// ============================================================================

#define BATCH 2
#define SEQ   2048
#define DM    768
#define NH    12
#define DKH   64
#define MTOK  (BATCH*SEQ)   // 4096

// bf16 hi/lo scratch
__device__ __nv_bfloat16 g_xh[MTOK*DM],  g_xl[MTOK*DM];
__device__ __nv_bfloat16 g_qh[MTOK*DM],  g_ql[MTOK*DM];
__device__ __nv_bfloat16 g_kh[MTOK*DM],  g_kl[MTOK*DM];
__device__ __nv_bfloat16 g_vh[MTOK*DM],  g_vl[MTOK*DM];
__device__ __nv_bfloat16 g_ch[MTOK*DM],  g_cl[MTOK*DM];
__device__ __nv_bfloat16 g_wqh[DM*DM], g_wql[DM*DM];
__device__ __nv_bfloat16 g_wkh[DM*DM], g_wkl[DM*DM];
__device__ __nv_bfloat16 g_wvh[DM*DM], g_wvl[DM*DM];
__device__ __nv_bfloat16 g_woh[DM*DM], g_wol[DM*DM];

// ----------------------------------------------------------------------------
// small helpers
// ----------------------------------------------------------------------------
__device__ __forceinline__ uint32_t smem_u32(const void* p) {
    uint32_t a;
    asm("{ .reg .u64 t; cvta.to.shared.u64 t, %1; cvt.u32.u64 %0, t; }"
        : "=r"(a) : "l"(p));
    return a;
}
__device__ __forceinline__ void cp16(uint32_t dst, const void* src) {
    asm volatile("cp.async.cg.shared.global [%0], [%1], 16;"
                 :: "r"(dst), "l"(src) : "memory");
}
__device__ __forceinline__ void ldsm4(uint32_t* r, uint32_t addr) {
    asm volatile("ldmatrix.sync.aligned.m8n8.x4.shared.b16 {%0,%1,%2,%3}, [%4];"
                 : "=r"(r[0]), "=r"(r[1]), "=r"(r[2]), "=r"(r[3]) : "r"(addr));
}
__device__ __forceinline__ void ldsm4t(uint32_t* r, uint32_t addr) {
    asm volatile("ldmatrix.sync.aligned.m8n8.x4.trans.shared.b16 {%0,%1,%2,%3}, [%4];"
                 : "=r"(r[0]), "=r"(r[1]), "=r"(r[2]), "=r"(r[3]) : "r"(addr));
}
__device__ __forceinline__ void mma16816(float* c, const uint32_t* a,
                                         uint32_t b0, uint32_t b1) {
    asm volatile(
        "mma.sync.aligned.m16n8k16.row.col.f32.bf16.bf16.f32 "
        "{%0,%1,%2,%3}, {%4,%5,%6,%7}, {%8,%9}, {%0,%1,%2,%3};"
        : "+f"(c[0]), "+f"(c[1]), "+f"(c[2]), "+f"(c[3])
        : "r"(a[0]), "r"(a[1]), "r"(a[2]), "r"(a[3]), "r"(b0), "r"(b1));
}
__device__ __forceinline__ uint32_t pack_hi(float a, float b) {
    __nv_bfloat162 t = __floats2bfloat162_rn(a, b);
    return *(uint32_t*)&t;
}
__device__ __forceinline__ uint32_t pack_lo(float a, float b, uint32_t hi) {
    __nv_bfloat162 h = *(__nv_bfloat162*)&hi;
    __nv_bfloat162 t = __floats2bfloat162_rn(a - __bfloat162float(h.x),
                                             b - __bfloat162float(h.y));
    return *(uint32_t*)&t;
}

// ----------------------------------------------------------------------------
// fp32 -> bf16 hi/lo split
// ----------------------------------------------------------------------------
__device__ __forceinline__ void cvt_hilo_body(
    const float* __restrict__ s, __nv_bfloat16* __restrict__ hi,
    __nv_bfloat16* __restrict__ lo, int n4, int i)
{
    if (i >= n4) return;
    float4 v = ((const float4*)s)[i];
    uint32_t h0 = pack_hi(v.x, v.y), h1 = pack_hi(v.z, v.w);
    uint32_t l0 = pack_lo(v.x, v.y, h0), l1 = pack_lo(v.z, v.w, h1);
    ((uint32_t*)hi)[2*i]   = h0;
    ((uint32_t*)hi)[2*i+1] = h1;
    ((uint32_t*)lo)[2*i]   = l0;
    ((uint32_t*)lo)[2*i+1] = l1;
}

__global__ void __launch_bounds__(256) cvt_hilo_kernel(
    const float* __restrict__ s, __nv_bfloat16* __restrict__ hi,
    __nv_bfloat16* __restrict__ lo, int n4)
{
    cvt_hilo_body(s, hi, lo, n4, blockIdx.x * blockDim.x + threadIdx.x);
}

__global__ void __launch_bounds__(256) cvt_w4_kernel(
    const float* __restrict__ s0, __nv_bfloat16* __restrict__ h0, __nv_bfloat16* __restrict__ l0,
    const float* __restrict__ s1, __nv_bfloat16* __restrict__ h1, __nv_bfloat16* __restrict__ l1,
    const float* __restrict__ s2, __nv_bfloat16* __restrict__ h2, __nv_bfloat16* __restrict__ l2,
    const float* __restrict__ s3, __nv_bfloat16* __restrict__ h3, __nv_bfloat16* __restrict__ l3,
    int n4)
{
    const float* s; __nv_bfloat16 *h, *l;
    switch (blockIdx.y) {
        case 0: s = s0; h = h0; l = l0; break;
        case 1: s = s1; h = h1; l = l1; break;
        case 2: s = s2; h = h2; l = l2; break;
        default: s = s3; h = h3; l = l3; break;
    }
    cvt_hilo_body(s, h, l, n4, blockIdx.x * blockDim.x + threadIdx.x);
}

// ----------------------------------------------------------------------------
// mma.sync bf16 3-split GEMM (unchanged from R6, passing).
// ----------------------------------------------------------------------------
#define MM_ROWB   80
#define MM_ARR    10240
#define MM_STAGE  (4*MM_ARR)
#define MM_SMEM   (2*MM_STAGE)

__device__ __forceinline__ void mm_load_chunk(
    const __nv_bfloat16* __restrict__ Ah, const __nv_bfloat16* __restrict__ Al,
    const __nv_bfloat16* __restrict__ Bh, const __nv_bfloat16* __restrict__ Bl,
    int m0, int n0, int k0, uint32_t stage, int tid)
{
    const __nv_bfloat16* srcs[4] = {Ah, Al, Bh, Bl};
    const int r0s[4] = {m0, m0, n0, n0};
#pragma unroll
    for (int a = 0; a < 4; a++) {
#pragma unroll
        for (int i = 0; i < 2; i++) {
            int f = tid + i * 256;
            int r = f >> 2;
            int c8 = (f & 3) * 8;
            cp16(stage + a * MM_ARR + r * MM_ROWB + c8 * 2,
                 srcs[a] + (size_t)(r0s[a] + r) * DM + k0 + c8);
        }
    }
    asm volatile("cp.async.commit_group;" ::: "memory");
}

template<bool BF16OUT>
__device__ __forceinline__ void tc_gemm_tile(
    const __nv_bfloat16* __restrict__ Ah, const __nv_bfloat16* __restrict__ Al,
    const __nv_bfloat16* __restrict__ Bh, const __nv_bfloat16* __restrict__ Bl,
    const float* __restrict__ bias, float* __restrict__ Yf,
    __nv_bfloat16* __restrict__ Yh, __nv_bfloat16* __restrict__ Yl, float scale,
    int m0, int n0, char* smem)
{
    const int tid  = threadIdx.x;
    const int wid  = tid >> 5;
    const int lane = tid & 31;
    const int wm   = wid >> 1;
    const int wn   = wid & 1;
    const uint32_t sbase = smem_u32(smem);

    float acc[16][4];
#pragma unroll
    for (int i = 0; i < 16; i++)
#pragma unroll
        for (int j = 0; j < 4; j++) acc[i][j] = 0.f;

    const int la_row = lane & 15, la_kh = (lane >> 4) * 8;
    const int lb_j = lane & 7, lb_sel = lane >> 3;
    const int lb_rowoff = (lb_sel >> 1) * 8 + lb_j;
    const int lb_kh = (lb_sel & 1) * 8;

    mm_load_chunk(Ah, Al, Bh, Bl, m0, n0, 0, sbase, tid);

    for (int c = 0; c < DM / 32; c++) {
        const uint32_t stage = sbase + (uint32_t)(c & 1) * MM_STAGE;
        if (c + 1 < DM / 32) {
            mm_load_chunk(Ah, Al, Bh, Bl, m0, n0, (c + 1) * 32,
                          sbase + (uint32_t)((c + 1) & 1) * MM_STAGE, tid);
            asm volatile("cp.async.wait_group 1;" ::: "memory");
        } else {
            asm volatile("cp.async.wait_group 0;" ::: "memory");
        }
        __syncthreads();

#pragma unroll
        for (int ks = 0; ks < 2; ks++) {
            const int k16 = ks * 16;
            uint32_t ah[2][4], al[2][4];
#pragma unroll
            for (int im = 0; im < 2; im++) {
                uint32_t ra = (uint32_t)((wm * 32 + im * 16 + la_row) * MM_ROWB
                                         + (k16 + la_kh) * 2);
                ldsm4(ah[im], stage + 0 * MM_ARR + ra);
                ldsm4(al[im], stage + 1 * MM_ARR + ra);
            }
#pragma unroll
            for (int bp = 0; bp < 4; bp++) {
                uint32_t rb = (uint32_t)((wn * 64 + bp * 16 + lb_rowoff) * MM_ROWB
                                         + (k16 + lb_kh) * 2);
                uint32_t bh[4], bl[4];
                ldsm4(bh, stage + 2 * MM_ARR + rb);
                ldsm4(bl, stage + 3 * MM_ARR + rb);
#pragma unroll
                for (int im = 0; im < 2; im++)
#pragma unroll
                    for (int fp = 0; fp < 2; fp++) {
                        float* cc = acc[im * 8 + bp * 2 + fp];
                        mma16816(cc, ah[im], bh[fp*2], bh[fp*2+1]);
                        mma16816(cc, ah[im], bl[fp*2], bl[fp*2+1]);
                        mma16816(cc, al[im], bh[fp*2], bh[fp*2+1]);
                    }
            }
        }
        __syncthreads();
    }

    const int rquad = lane >> 2, cpair = (lane & 3) * 2;
#pragma unroll
    for (int im = 0; im < 2; im++)
#pragma unroll
        for (int bp = 0; bp < 4; bp++)
#pragma unroll
            for (int fp = 0; fp < 2; fp++) {
                const float* cc = acc[im * 8 + bp * 2 + fp];
                int m = m0 + wm * 32 + im * 16 + rquad;
                int n = n0 + wn * 64 + bp * 16 + fp * 8 + cpair;
                float b0 = bias[n], b1 = bias[n + 1];
                if (BF16OUT) {
                    float e0 = (cc[0] + b0) * scale, e1 = (cc[1] + b1) * scale;
                    float e2 = (cc[2] + b0) * scale, e3 = (cc[3] + b1) * scale;
                    uint32_t h0 = pack_hi(e0, e1), h1 = pack_hi(e2, e3);
                    *(uint32_t*)&Yh[(size_t)m * DM + n]       = h0;
                    *(uint32_t*)&Yl[(size_t)m * DM + n]       = pack_lo(e0, e1, h0);
                    *(uint32_t*)&Yh[(size_t)(m + 8) * DM + n] = h1;
                    *(uint32_t*)&Yl[(size_t)(m + 8) * DM + n] = pack_lo(e2, e3, h1);
                } else {
                    float2 o0 = make_float2(cc[0] + b0, cc[1] + b1);
                    float2 o1 = make_float2(cc[2] + b0, cc[3] + b1);
                    *(float2*)&Yf[(size_t)m * DM + n]       = o0;
                    *(float2*)&Yf[(size_t)(m + 8) * DM + n] = o1;
                }
            }
}

__global__ void __launch_bounds__(256) tc_qkv_kernel(
    const __nv_bfloat16* __restrict__ Xh, const __nv_bfloat16* __restrict__ Xl,
    const __nv_bfloat16* __restrict__ Wqh, const __nv_bfloat16* __restrict__ Wql,
    const float* __restrict__ bq,
    __nv_bfloat16* __restrict__ Qh, __nv_bfloat16* __restrict__ Ql,
    const __nv_bfloat16* __restrict__ Wkh, const __nv_bfloat16* __restrict__ Wkl,
    const float* __restrict__ bk,
    __nv_bfloat16* __restrict__ Kh, __nv_bfloat16* __restrict__ Kl,
    const __nv_bfloat16* __restrict__ Wvh, const __nv_bfloat16* __restrict__ Wvl,
    const float* __restrict__ bv,
    __nv_bfloat16* __restrict__ Vh, __nv_bfloat16* __restrict__ Vl)
{
    extern __shared__ char smem[];
    const __nv_bfloat16 *Wh, *Wl; const float* b;
    __nv_bfloat16 *Yh, *Yl; float scale;
    if (blockIdx.z == 0)      { Wh = Wqh; Wl = Wql; b = bq; Yh = Qh; Yl = Ql; scale = 0.125f; }
    else if (blockIdx.z == 1) { Wh = Wkh; Wl = Wkl; b = bk; Yh = Kh; Yl = Kl; scale = 1.f; }
    else                      { Wh = Wvh; Wl = Wvl; b = bv; Yh = Vh; Yl = Vl; scale = 1.f; }
    tc_gemm_tile<true>(Xh, Xl, Wh, Wl, b, nullptr, Yh, Yl, scale,
                       blockIdx.y * 128, blockIdx.x * 128, smem);
}

__global__ void __launch_bounds__(256) tc_out_kernel(
    const __nv_bfloat16* __restrict__ Ah, const __nv_bfloat16* __restrict__ Al,
    const __nv_bfloat16* __restrict__ Wh, const __nv_bfloat16* __restrict__ Wl,
    const float* __restrict__ b, float* __restrict__ Y)
{
    extern __shared__ char smem[];
    tc_gemm_tile<false>(Ah, Al, Wh, Wl, b, Y, nullptr, nullptr, 1.f,
                        blockIdx.y * 128, blockIdx.x * 128, smem);
}

// ----------------------------------------------------------------------------
// Flash attention on mma.sync — R7: K-tile 64, 2 CTAs/SM.
// CTA: 128 queries x one (b,h); 8 warps x 16 rows. Q in smem (frags reloaded
// per tile), K/V hi/lo double-buffered 64-key stages.
// ----------------------------------------------------------------------------
#define AT_ROWB 144
#define AT_QARR (128*AT_ROWB)            // 18432
#define AT_KARR (64*AT_ROWB)             // 9216
#define AT_ST0  (2*AT_QARR)              // 36864
#define AT_STSZ (4*AT_KARR)              // 36864
#define AT_SMEM (AT_ST0 + 2*AT_STSZ)     // 110592

__device__ __forceinline__ void at_load_q(
    const __nv_bfloat16* __restrict__ src, uint32_t dst, int tok0, int h, int tid)
{
#pragma unroll
    for (int i = 0; i < 4; i++) {
        int f = tid + i * 256;        // 0..1023 (128 rows x 8 col-chunks)
        int r = f >> 3, c = f & 7;
        cp16(dst + r * AT_ROWB + c * 16,
             src + (size_t)(tok0 + r) * DM + h * DKH + c * 8);
    }
}
__device__ __forceinline__ void at_load_kv(
    const __nv_bfloat16* __restrict__ src, uint32_t dst, int tok0, int h, int tid)
{
#pragma unroll
    for (int i = 0; i < 2; i++) {
        int f = tid + i * 256;        // 0..511 (64 rows x 8 col-chunks)
        int r = f >> 3, c = f & 7;
        cp16(dst + r * AT_ROWB + c * 16,
             src + (size_t)(tok0 + r) * DM + h * DKH + c * 8);
    }
}

__global__ void __launch_bounds__(256, 2) attn_mma_kernel(
    const __nv_bfloat16* __restrict__ Qh, const __nv_bfloat16* __restrict__ Ql,
    const __nv_bfloat16* __restrict__ Kh, const __nv_bfloat16* __restrict__ Kl,
    const __nv_bfloat16* __restrict__ Vh, const __nv_bfloat16* __restrict__ Vl,
    __nv_bfloat16* __restrict__ Ch, __nv_bfloat16* __restrict__ Cl)
{
    extern __shared__ char smem[];
    const uint32_t sb = smem_u32(smem);
    const int tid = threadIdx.x, wid = tid >> 5, lane = tid & 31;
    const int b = blockIdx.z, h = blockIdx.y, q0 = blockIdx.x * 128;
    const int tokQ = b * SEQ + q0, tokK = b * SEQ;

    // Q tiles (group 0)
    at_load_q(Qh, sb,           tokQ, h, tid);
    at_load_q(Ql, sb + AT_QARR, tokQ, h, tid);
    asm volatile("cp.async.commit_group;" ::: "memory");
    // stage 0 K/V (group 1)
    {
        uint32_t st = sb + AT_ST0;
        at_load_kv(Kh, st,             tokK, h, tid);
        at_load_kv(Kl, st + AT_KARR,   tokK, h, tid);
        at_load_kv(Vh, st + 2*AT_KARR, tokK, h, tid);
        at_load_kv(Vl, st + 3*AT_KARR, tokK, h, tid);
        asm volatile("cp.async.commit_group;" ::: "memory");
    }

    float of[8][4];
#pragma unroll
    for (int i = 0; i < 8; i++)
#pragma unroll
        for (int j = 0; j < 4; j++) of[i][j] = 0.f;
    float m0 = -INFINITY, m1 = -INFINITY, l0 = 0.f, l1 = 0.f;

    const int la_row = lane & 15, la_k = (lane >> 4) * 8;
    const int lb_j = lane & 7, lb_sel = lane >> 3;
    const int lb_row = (lb_sel >> 1) * 8 + lb_j;
    const int lb_k = (lb_sel & 1) * 8;

    for (int kt = 0; kt < 32; kt++) {
        const uint32_t stg = sb + AT_ST0 + (uint32_t)(kt & 1) * AT_STSZ;
        if (kt < 31) {
            uint32_t nst = sb + AT_ST0 + (uint32_t)((kt + 1) & 1) * AT_STSZ;
            int tk = tokK + (kt + 1) * 64;
            at_load_kv(Kh, nst,             tk, h, tid);
            at_load_kv(Kl, nst + AT_KARR,   tk, h, tid);
            at_load_kv(Vh, nst + 2*AT_KARR, tk, h, tid);
            at_load_kv(Vl, nst + 3*AT_KARR, tk, h, tid);
            asm volatile("cp.async.commit_group;" ::: "memory");
            asm volatile("cp.async.wait_group 1;" ::: "memory");
        } else {
            asm volatile("cp.async.wait_group 0;" ::: "memory");
        }
        __syncthreads();

        // ---- S = Q K^T (3-split): 16 rows x 64 keys per warp
        float sf[8][4];
#pragma unroll
        for (int i = 0; i < 8; i++)
#pragma unroll
            for (int j = 0; j < 4; j++) sf[i][j] = 0.f;

#pragma unroll
        for (int kc = 0; kc < 4; kc++) {
            uint32_t qa = sb + (uint32_t)((wid * 16 + la_row) * AT_ROWB
                                          + (kc * 16 + la_k) * 2);
            uint32_t qh4[4], ql4[4];
            ldsm4(qh4, qa);
            ldsm4(ql4, qa + AT_QARR);
#pragma unroll
            for (int kn = 0; kn < 4; kn++) {
                uint32_t ka = stg + (uint32_t)((kn * 16 + lb_row) * AT_ROWB
                                               + (kc * 16 + lb_k) * 2);
                uint32_t bh4[4], bl4[4];
                ldsm4(bh4, ka);
                ldsm4(bl4, ka + AT_KARR);
#pragma unroll
                for (int nb = 0; nb < 2; nb++) {
                    mma16816(sf[2*kn+nb], qh4, bh4[nb*2], bh4[nb*2+1]);
                    mma16816(sf[2*kn+nb], qh4, bl4[nb*2], bl4[nb*2+1]);
                    mma16816(sf[2*kn+nb], ql4, bh4[nb*2], bh4[nb*2+1]);
                }
            }
        }

        // ---- online softmax (rows rquad and rquad+8; 4 lanes per row)
        float mx0 = -INFINITY, mx1 = -INFINITY;
#pragma unroll
        for (int j = 0; j < 8; j++) {
            mx0 = fmaxf(mx0, fmaxf(sf[j][0], sf[j][1]));
            mx1 = fmaxf(mx1, fmaxf(sf[j][2], sf[j][3]));
        }
        mx0 = fmaxf(mx0, __shfl_xor_sync(0xffffffffu, mx0, 1));
        mx0 = fmaxf(mx0, __shfl_xor_sync(0xffffffffu, mx0, 2));
        mx1 = fmaxf(mx1, __shfl_xor_sync(0xffffffffu, mx1, 1));
        mx1 = fmaxf(mx1, __shfl_xor_sync(0xffffffffu, mx1, 2));
        const float m0n = fmaxf(m0, mx0), m1n = fmaxf(m1, mx1);
        const float c0 = __expf(m0 - m0n), c1 = __expf(m1 - m1n);
#pragma unroll
        for (int j = 0; j < 8; j++) {
            of[j][0] *= c0; of[j][1] *= c0;
            of[j][2] *= c1; of[j][3] *= c1;
        }
        float rs0 = 0.f, rs1 = 0.f;
#pragma unroll
        for (int j = 0; j < 8; j++) {
            sf[j][0] = __expf(sf[j][0] - m0n); rs0 += sf[j][0];
            sf[j][1] = __expf(sf[j][1] - m0n); rs0 += sf[j][1];
            sf[j][2] = __expf(sf[j][2] - m1n); rs1 += sf[j][2];
            sf[j][3] = __expf(sf[j][3] - m1n); rs1 += sf[j][3];
        }
        rs0 += __shfl_xor_sync(0xffffffffu, rs0, 1);
        rs0 += __shfl_xor_sync(0xffffffffu, rs0, 2);
        rs1 += __shfl_xor_sync(0xffffffffu, rs1, 1);
        rs1 += __shfl_xor_sync(0xffffffffu, rs1, 2);
        l0 = l0 * c0 + rs0;
        l1 = l1 * c1 + rs1;
        m0 = m0n; m1 = m1n;

        // ---- O += P V (3-split: PhVh + PlVh + PhVl)
#pragma unroll
        for (int kc = 0; kc < 4; kc++) {
            uint32_t ph[4], pl[4];
            ph[0] = pack_hi(sf[2*kc][0],   sf[2*kc][1]);
            ph[1] = pack_hi(sf[2*kc][2],   sf[2*kc][3]);
            ph[2] = pack_hi(sf[2*kc+1][0], sf[2*kc+1][1]);
            ph[3] = pack_hi(sf[2*kc+1][2], sf[2*kc+1][3]);
            pl[0] = pack_lo(sf[2*kc][0],   sf[2*kc][1],   ph[0]);
            pl[1] = pack_lo(sf[2*kc][2],   sf[2*kc][3],   ph[1]);
            pl[2] = pack_lo(sf[2*kc+1][0], sf[2*kc+1][1], ph[2]);
            pl[3] = pack_lo(sf[2*kc+1][2], sf[2*kc+1][3], ph[3]);
#pragma unroll
            for (int dn = 0; dn < 4; dn++) {
                uint32_t va = stg + 2*AT_KARR
                            + (uint32_t)((kc * 16 + la_row) * AT_ROWB
                                         + (dn * 16 + la_k) * 2);
                uint32_t vh4[4], vl4[4];
                ldsm4t(vh4, va);
                ldsm4t(vl4, va + AT_KARR);
#pragma unroll
                for (int db = 0; db < 2; db++) {
                    float* o = of[dn * 2 + db];
                    mma16816(o, ph, vh4[db*2], vh4[db*2+1]);
                    mma16816(o, pl, vh4[db*2], vh4[db*2+1]);
                    mma16816(o, ph, vl4[db*2], vl4[db*2+1]);
                }
            }
        }
        __syncthreads();
    }

    // ---- epilogue: O/l -> ctx bf16 hi/lo
    const float i0 = 1.f / l0, i1 = 1.f / l1;
    const int rquad = lane >> 2, cpair = (lane & 3) * 2;
    const int tok = tokQ + wid * 16 + rquad;
#pragma unroll
    for (int j = 0; j < 8; j++) {
        int col = h * DKH + j * 8 + cpair;
        float e0 = of[j][0] * i0, e1 = of[j][1] * i0;
        float e2 = of[j][2] * i1, e3 = of[j][3] * i1;
        uint32_t h0 = pack_hi(e0, e1), h1 = pack_hi(e2, e3);
        *(uint32_t*)&Ch[(size_t)tok * DM + col]       = h0;
        *(uint32_t*)&Cl[(size_t)tok * DM + col]       = pack_lo(e0, e1, h0);
        *(uint32_t*)&Ch[(size_t)(tok + 8) * DM + col] = h1;
        *(uint32_t*)&Cl[(size_t)(tok + 8) * DM + col] = pack_lo(e2, e3, h1);
    }
}

// ----------------------------------------------------------------------------
// Launch
// ----------------------------------------------------------------------------
extern "C" void kernel_launch(void* const* d_in, const int* in_sizes, int n_in,
                              void* d_out, int out_size)
{
    (void)in_sizes; (void)n_in; (void)out_size;
    const float* x   = (const float*)d_in[0];
    const float* w_q = (const float*)d_in[1];
    const float* b_q = (const float*)d_in[2];
    const float* w_k = (const float*)d_in[3];
    const float* b_k = (const float*)d_in[4];
    const float* w_v = (const float*)d_in[5];
    const float* b_v = (const float*)d_in[6];
    const float* w_o = (const float*)d_in[7];
    const float* b_o = (const float*)d_in[8];
    float* out = (float*)d_out;

    __nv_bfloat16 *xh, *xl, *qh, *ql, *kh, *kl, *vh, *vl, *ch, *cl;
    __nv_bfloat16 *wqh, *wql, *wkh, *wkl, *wvh, *wvl, *woh, *wol;
    cudaGetSymbolAddress((void**)&xh, g_xh);   cudaGetSymbolAddress((void**)&xl, g_xl);
    cudaGetSymbolAddress((void**)&qh, g_qh);   cudaGetSymbolAddress((void**)&ql, g_ql);
    cudaGetSymbolAddress((void**)&kh, g_kh);   cudaGetSymbolAddress((void**)&kl, g_kl);
    cudaGetSymbolAddress((void**)&vh, g_vh);   cudaGetSymbolAddress((void**)&vl, g_vl);
    cudaGetSymbolAddress((void**)&ch, g_ch);   cudaGetSymbolAddress((void**)&cl, g_cl);
    cudaGetSymbolAddress((void**)&wqh, g_wqh); cudaGetSymbolAddress((void**)&wql, g_wql);
    cudaGetSymbolAddress((void**)&wkh, g_wkh); cudaGetSymbolAddress((void**)&wkl, g_wkl);
    cudaGetSymbolAddress((void**)&wvh, g_wvh); cudaGetSymbolAddress((void**)&wvl, g_wvl);
    cudaGetSymbolAddress((void**)&woh, g_woh); cudaGetSymbolAddress((void**)&wol, g_wol);

    const int NX4 = MTOK * DM / 4;
    const int NW4 = DM * DM / 4;
    cvt_hilo_kernel<<<(NX4 + 255) / 256, 256>>>(x, xh, xl, NX4);
    dim3 gw((NW4 + 255) / 256, 4);
    cvt_w4_kernel<<<gw, 256>>>(w_q, wqh, wql, w_k, wkh, wkl,
                               w_v, wvh, wvl, w_o, woh, wol, NW4);

    cudaFuncSetAttribute(tc_qkv_kernel,
                         cudaFuncAttributeMaxDynamicSharedMemorySize, MM_SMEM);
    cudaFuncSetAttribute(tc_out_kernel,
                         cudaFuncAttributeMaxDynamicSharedMemorySize, MM_SMEM);
    cudaFuncSetAttribute(attn_mma_kernel,
                         cudaFuncAttributeMaxDynamicSharedMemorySize, AT_SMEM);

    dim3 gqkv(DM / 128, MTOK / 128, 3);
    tc_qkv_kernel<<<gqkv, 256, MM_SMEM>>>(
        xh, xl, wqh, wql, b_q, qh, ql, wkh, wkl, b_k, kh, kl,
        wvh, wvl, b_v, vh, vl);

    attn_mma_kernel<<<dim3(SEQ / 128, NH, BATCH), 256, AT_SMEM>>>(
        qh, ql, kh, kl, vh, vl, ch, cl);

    dim3 go(DM / 128, MTOK / 128);
    tc_out_kernel<<<go, 256, MM_SMEM>>>(ch, cl, woh, wol, b_o, out);
}